// round 4
// baseline (speedup 1.0000x reference)
#include <cuda_runtime.h>
#include <cuda_bf16.h>
#include <math.h>

#define D_MODEL 2048
#define T_SEQ   2048
#define NQH     32
#define NKVH    8
#define HD      64
#define DIM_KV  512

// Scratch (allocation-free rule: __device__ globals)
__device__ float g_Q[T_SEQ * D_MODEL];
__device__ float g_K[T_SEQ * DIM_KV];
__device__ float g_V[T_SEQ * DIM_KV];
__device__ float g_O[T_SEQ * D_MODEL];

// ---------------------------------------------------------------------------
// SGEMM: C[M,N] = A[M,K] @ B[K,N], row-major. 128x128x8 block tile,
// 256 threads, 8x8 per-thread micro-tile.
// ---------------------------------------------------------------------------
__global__ __launch_bounds__(256) void sgemm_kernel(
    int M, int N, int K,
    const float* __restrict__ A, const float* __restrict__ B,
    float* __restrict__ C)
{
    const int BM = 128, BN = 128, BK = 8, TM = 8, TN = 8;
    __shared__ float As[BK * BM];   // transposed: As[k][m]
    __shared__ float Bs[BK * BN];

    int tid  = threadIdx.x;
    int cRow = blockIdx.y, cCol = blockIdx.x;
    int threadCol = tid % (BN / TN);   // 0..15
    int threadRow = tid / (BN / TN);   // 0..15

    const float* Ab = A + (size_t)cRow * BM * K;
    const float* Bb = B + (size_t)cCol * BN;
    float* Cb = C + (size_t)cRow * BM * N + (size_t)cCol * BN;

    int innerRowA = tid / 2;            // 0..127
    int innerColA = (tid % 2) * 4;      // 0 or 4
    int innerRowB = tid / 32;           // 0..7
    int innerColB = (tid % 32) * 4;     // 0..124

    float acc[TM * TN];
    #pragma unroll
    for (int i = 0; i < TM * TN; i++) acc[i] = 0.0f;
    float regM[TM], regN[TN];

    for (int bk = 0; bk < K; bk += BK) {
        float4 a4 = *(const float4*)(Ab + (size_t)innerRowA * K + bk + innerColA);
        As[(innerColA + 0) * BM + innerRowA] = a4.x;
        As[(innerColA + 1) * BM + innerRowA] = a4.y;
        As[(innerColA + 2) * BM + innerRowA] = a4.z;
        As[(innerColA + 3) * BM + innerRowA] = a4.w;
        *(float4*)(&Bs[innerRowB * BN + innerColB]) =
            *(const float4*)(Bb + (size_t)(bk + innerRowB) * N + innerColB);
        __syncthreads();

        #pragma unroll
        for (int k = 0; k < BK; k++) {
            #pragma unroll
            for (int i = 0; i < TM; i++) regM[i] = As[k * BM + threadRow * TM + i];
            #pragma unroll
            for (int j = 0; j < TN; j++) regN[j] = Bs[k * BN + threadCol * TN + j];
            #pragma unroll
            for (int i = 0; i < TM; i++)
                #pragma unroll
                for (int j = 0; j < TN; j++)
                    acc[i * TN + j] += regM[i] * regN[j];
        }
        __syncthreads();
    }

    #pragma unroll
    for (int i = 0; i < TM; i++) {
        #pragma unroll
        for (int j = 0; j < TN; j += 4) {
            float4 o;
            o.x = acc[i * TN + j + 0];
            o.y = acc[i * TN + j + 1];
            o.z = acc[i * TN + j + 2];
            o.w = acc[i * TN + j + 3];
            *(float4*)(Cb + (size_t)(threadRow * TM + i) * N + threadCol * TN + j) = o;
        }
    }
}

// ---------------------------------------------------------------------------
// RoPE (interleaved pairs), in-place on [T, nheads*64].
// Angle computed exactly as the reference: inv_freq and t*inv_freq quantized
// to fp32, then accurate sin/cos (double) of that fp32 value.
// ---------------------------------------------------------------------------
__global__ void rope_kernel(float* __restrict__ X, int nheads, int rowstride)
{
    int idx = blockIdx.x * blockDim.x + threadIdx.x;
    int total = T_SEQ * nheads * (HD / 2);
    if (idx >= total) return;
    int i  = idx % (HD / 2);          // pair index 0..31
    int tmp = idx / (HD / 2);
    int h  = tmp % nheads;
    int t  = tmp / nheads;

    // reference: inv_freq = 500000^(-(2i)/64) in fp32; ang = t * inv_freq in fp32
    float invf = (float)pow(500000.0, -(double)i / 32.0);
    float angf = (float)t * invf;
    double ang = (double)angf;
    float c = (float)cos(ang);
    float s = (float)sin(ang);

    float* p = X + (size_t)t * rowstride + h * HD + 2 * i;
    float x1 = p[0], x2 = p[1];
    p[0] = x1 * c - x2 * s;
    p[1] = x1 * s + x2 * c;
}

// ---------------------------------------------------------------------------
// Causal flash attention, fp32. One block = 128 query rows x 1 head.
// One thread = one query row; q and accumulator in registers.
// K/V tiles (64 keys x 64 dim) staged in smem. Finite sentinel (-1e30),
// no inf arithmetic anywhere.
// ---------------------------------------------------------------------------
__global__ __launch_bounds__(128) void flash_kernel(
    const float* __restrict__ Q, const float* __restrict__ Kb,
    const float* __restrict__ Vb, float* __restrict__ O)
{
    const int BM = 128, BKV = 64;
    const float NEG = -1e30f;
    __shared__ float Ks[BKV][HD];
    __shared__ float Vs[BKV][HD];

    int h   = blockIdx.y;
    int kvh = h >> 2;                 // 4 q-heads per kv-head
    int m0  = blockIdx.x * BM;
    int r   = m0 + threadIdx.x;       // this thread's query row

    float q[HD];
    const float* qrow = Q + (size_t)r * D_MODEL + h * HD;
    #pragma unroll
    for (int d = 0; d < HD; d += 4) {
        float4 t4 = *(const float4*)(qrow + d);
        q[d] = t4.x; q[d + 1] = t4.y; q[d + 2] = t4.z; q[d + 3] = t4.w;
    }

    float acc[HD];
    #pragma unroll
    for (int d = 0; d < HD; d++) acc[d] = 0.0f;
    float m = NEG, l = 0.0f;
    const float scale = 0.125f;       // 1/sqrt(64)

    int kend = m0 + BM;               // causal: only tiles with keys <= last row
    for (int j0 = 0; j0 < kend; j0 += BKV) {
        // cooperative K/V tile load: 64x64 floats each -> 1024 float4 each
        #pragma unroll
        for (int u = 0; u < 8; u++) {
            int idx = threadIdx.x + u * 128;      // 0..1023
            int row = idx >> 4;
            int c4  = (idx & 15) << 2;
            const float* ksrc = Kb + (size_t)(j0 + row) * DIM_KV + kvh * HD + c4;
            const float* vsrc = Vb + (size_t)(j0 + row) * DIM_KV + kvh * HD + c4;
            *(float4*)(&Ks[row][c4]) = *(const float4*)ksrc;
            *(float4*)(&Vs[row][c4]) = *(const float4*)vsrc;
        }
        __syncthreads();

        #pragma unroll
        for (int jc = 0; jc < BKV; jc += 16) {
            float s[16];
            #pragma unroll
            for (int jj = 0; jj < 16; jj++) {
                const float* kr = &Ks[jc + jj][0];
                float sum = 0.0f;
                #pragma unroll
                for (int d = 0; d < HD; d++) sum += q[d] * kr[d];
                sum *= scale;
                s[jj] = ((j0 + jc + jj) <= r) ? sum : NEG;
            }
            float tmax = s[0];
            #pragma unroll
            for (int jj = 1; jj < 16; jj++) tmax = fmaxf(tmax, s[jj]);
            float mn = fmaxf(m, tmax);
            float corr = __expf(m - mn);   // first chunk: exp(-1e30) -> 0
            m = mn;
            float lsum = 0.0f;
            #pragma unroll
            for (int jj = 0; jj < 16; jj++) {
                s[jj] = __expf(s[jj] - mn);   // masked: exp(~-1e30) -> 0
                lsum += s[jj];
            }
            l = l * corr + lsum;
            #pragma unroll
            for (int d = 0; d < HD; d++) acc[d] *= corr;
            #pragma unroll
            for (int jj = 0; jj < 16; jj++) {
                float pv = s[jj];
                const float* vr = &Vs[jc + jj][0];
                #pragma unroll
                for (int d = 0; d < HD; d++) acc[d] += pv * vr[d];
            }
        }
        __syncthreads();
    }

    float invl = 1.0f / l;
    float* orow = O + (size_t)r * D_MODEL + h * HD;
    #pragma unroll
    for (int d = 0; d < HD; d += 4) {
        float4 o;
        o.x = acc[d] * invl; o.y = acc[d + 1] * invl;
        o.z = acc[d + 2] * invl; o.w = acc[d + 3] * invl;
        *(float4*)(orow + d) = o;
    }
}

// ---------------------------------------------------------------------------
// Launch. Handles BOTH possible input orderings, detected via in_sizes:
//   dict order:        q_embs, k_embs, v_embs, w_q, w_k, w_v, w_o
//                      sizes: 4M, 4M, 4M, 4M, 1M, 1M, 4M
//   alphabetical:      k_embs, q_embs, v_embs, w_k, w_o, w_q, w_v
//                      sizes: 4M, 4M, 4M, 1M, 4M, 4M, 1M
// Distinguish by in_sizes[3] (w_q: 4,194,304 vs w_k: 1,048,576).
// ---------------------------------------------------------------------------
extern "C" void kernel_launch(void* const* d_in, const int* in_sizes, int n_in,
                              void* d_out, int out_size)
{
    const float *q_embs, *k_embs, *v_embs, *w_q, *w_k, *w_v, *w_o;
    if (in_sizes[3] == D_MODEL * DIM_KV) {
        // alphabetical ordering
        k_embs = (const float*)d_in[0];
        q_embs = (const float*)d_in[1];
        v_embs = (const float*)d_in[2];
        w_k    = (const float*)d_in[3];
        w_o    = (const float*)d_in[4];
        w_q    = (const float*)d_in[5];
        w_v    = (const float*)d_in[6];
    } else {
        // dict (declaration) ordering
        q_embs = (const float*)d_in[0];
        k_embs = (const float*)d_in[1];
        v_embs = (const float*)d_in[2];
        w_q    = (const float*)d_in[3];
        w_k    = (const float*)d_in[4];
        w_v    = (const float*)d_in[5];
        w_o    = (const float*)d_in[6];
    }
    float* out = (float*)d_out;

    float *Q, *K, *V, *O;
    cudaGetSymbolAddress((void**)&Q, g_Q);
    cudaGetSymbolAddress((void**)&K, g_K);
    cudaGetSymbolAddress((void**)&V, g_V);
    cudaGetSymbolAddress((void**)&O, g_O);

    // Projections
    sgemm_kernel<<<dim3(D_MODEL / 128, T_SEQ / 128), 256>>>(T_SEQ, D_MODEL, D_MODEL, q_embs, w_q, Q);
    sgemm_kernel<<<dim3(DIM_KV / 128, T_SEQ / 128), 256>>>(T_SEQ, DIM_KV, D_MODEL, k_embs, w_k, K);
    sgemm_kernel<<<dim3(DIM_KV / 128, T_SEQ / 128), 256>>>(T_SEQ, DIM_KV, D_MODEL, v_embs, w_v, V);

    // RoPE on Q and K
    {
        int totQ = T_SEQ * NQH * (HD / 2);
        rope_kernel<<<(totQ + 255) / 256, 256>>>(Q, NQH, D_MODEL);
        int totK = T_SEQ * NKVH * (HD / 2);
        rope_kernel<<<(totK + 255) / 256, 256>>>(K, NKVH, DIM_KV);
    }

    // Causal GQA attention
    flash_kernel<<<dim3(T_SEQ / 128, NQH), 128>>>(Q, K, V, O);

    // Output projection
    sgemm_kernel<<<dim3(D_MODEL / 128, T_SEQ / 128), 256>>>(T_SEQ, D_MODEL, D_MODEL, O, w_o, out);
}

// round 6
// speedup vs baseline: 1.6337x; 1.6337x over previous
#include <cuda_runtime.h>
#include <cuda_bf16.h>
#include <math.h>
#include <stdint.h>

#define D_MODEL 2048
#define T_SEQ   2048
#define NQH     32
#define NKVH    8
#define HD      64
#define DIM_KV  512
#define KDIM    2048            // inner dim of every projection GEMM
#define K2DIM   (3*KDIM)        // split-bf16 expanded K = 6144
#define PADH    72              // smem row stride in halves (144B -> conflict-free ldmatrix)

// ---------------------------------------------------------------------------
// Device-global scratch (allocation-free rule)
// ---------------------------------------------------------------------------
__device__ float g_Q[T_SEQ * D_MODEL];
__device__ float g_K[T_SEQ * DIM_KV];
__device__ float g_V[T_SEQ * DIM_KV];
__device__ float g_O[T_SEQ * D_MODEL];
__device__ __nv_bfloat16 g_A2[T_SEQ  * K2DIM];   // split activations [M, 3K]
__device__ __nv_bfloat16 g_B2[D_MODEL * K2DIM];  // split weights^T  [N, 3K]
__device__ float g_rc[T_SEQ * 32];               // rope cos table
__device__ float g_rs[T_SEQ * 32];               // rope sin table

// ---------------------------------------------------------------------------
// PTX helpers: portable sm_80+ instructions only (HMMA path; no tcgen05)
// ---------------------------------------------------------------------------
__device__ __forceinline__ uint32_t smem_u32(const void* p) {
    uint32_t a;
    asm("{ .reg .u64 t; cvta.to.shared.u64 t, %1; cvt.u32.u64 %0, t; }"
        : "=r"(a) : "l"(p));
    return a;
}

__device__ __forceinline__ void ldmatrix_x4(uint32_t& r0, uint32_t& r1,
                                            uint32_t& r2, uint32_t& r3,
                                            uint32_t addr) {
    asm volatile("ldmatrix.sync.aligned.m8n8.x4.shared.b16 {%0,%1,%2,%3}, [%4];"
                 : "=r"(r0), "=r"(r1), "=r"(r2), "=r"(r3) : "r"(addr));
}

__device__ __forceinline__ void mma16816(float* d, const uint32_t* a,
                                         uint32_t b0, uint32_t b1) {
    asm volatile(
        "mma.sync.aligned.m16n8k16.row.col.f32.bf16.bf16.f32 "
        "{%0,%1,%2,%3}, {%4,%5,%6,%7}, {%8,%9}, {%0,%1,%2,%3};"
        : "+f"(d[0]), "+f"(d[1]), "+f"(d[2]), "+f"(d[3])
        : "r"(a[0]), "r"(a[1]), "r"(a[2]), "r"(a[3]), "r"(b0), "r"(b1));
}

__device__ __forceinline__ void cp_async16(uint32_t saddr, const void* gaddr) {
    asm volatile("cp.async.cg.shared.global [%0], [%1], 16;"
                 :: "r"(saddr), "l"(gaddr));
}
#define CP_COMMIT() asm volatile("cp.async.commit_group;" ::: "memory")
#define CP_WAIT(n)  asm volatile("cp.async.wait_group %0;" :: "n"(n) : "memory")

// ---------------------------------------------------------------------------
// Split-bf16 conversion kernels
//   A' [M, 3K]: [hi(X) | lo(X) | hi(X)]
//   B' [N, 3K]: [hi(W^T) | hi(W^T) | lo(W^T)]
//   => A'·B'^T = Ah·Wh + Al·Wh + Ah·Wl ≈ X·W  (err ~2^-16)
// ---------------------------------------------------------------------------
__global__ void split_a_kernel(const float* __restrict__ X,
                               __nv_bfloat16* __restrict__ A2, int M)
{
    int idx = blockIdx.x * blockDim.x + threadIdx.x;
    if (idx >= M * KDIM) return;
    int m = idx / KDIM, k = idx % KDIM;
    float x = X[idx];
    __nv_bfloat16 h = __float2bfloat16(x);
    __nv_bfloat16 l = __float2bfloat16(x - __bfloat162float(h));
    size_t b = (size_t)m * K2DIM;
    A2[b + k]            = h;
    A2[b + KDIM + k]     = l;
    A2[b + 2 * KDIM + k] = h;
}

__global__ void split_b_kernel(const float* __restrict__ W,
                               __nv_bfloat16* __restrict__ B2, int N)
{
    __shared__ float tile[32][33];
    int n0 = blockIdx.x * 32, k0 = blockIdx.y * 32;
    int tx = threadIdx.x, ty = threadIdx.y;   // 32 x 8
    #pragma unroll
    for (int i = 0; i < 32; i += 8)
        tile[ty + i][tx] = W[(size_t)(k0 + ty + i) * N + n0 + tx];
    __syncthreads();
    #pragma unroll
    for (int i = 0; i < 32; i += 8) {
        int n = n0 + ty + i;
        float x = tile[tx][ty + i];           // = W[k0+tx][n]
        __nv_bfloat16 h = __float2bfloat16(x);
        __nv_bfloat16 l = __float2bfloat16(x - __bfloat162float(h));
        size_t b = (size_t)n * K2DIM;
        B2[b + k0 + tx]            = h;
        B2[b + KDIM + k0 + tx]     = h;
        B2[b + 2 * KDIM + k0 + tx] = l;
    }
}

// ---------------------------------------------------------------------------
// HMMA GEMM: C[M,N] = A2[M,3K] @ B2[N,3K]^T, fp32 accumulate.
// CTA tile 128x128, K-chunk 64 (bf16), 256 threads = 8 warps (2x4),
// warp tile 64x32, mma.m16n8k16, cp.async double-buffered smem.
// SMEM rows padded to 72 halves (144B) -> ldmatrix conflict-free.
// ---------------------------------------------------------------------------
#define GEMM_SMEM_BYTES (4 * 128 * PADH * 2)   // 73728

__device__ __forceinline__ void ldgsts_tile(uint32_t sBase,
                                            const __nv_bfloat16* G,
                                            int k0, int tid)
{
    // 128 rows x 64 halves = 1024 x 16B chunks; 4 per thread
    #pragma unroll
    for (int i = 0; i < 4; i++) {
        int id  = tid + (i << 8);
        int row = id >> 3;
        int c8  = id & 7;
        cp_async16(sBase + (uint32_t)(row * PADH + c8 * 8) * 2,
                   G + (size_t)row * K2DIM + k0 + c8 * 8);
    }
}

__global__ __launch_bounds__(256) void gemm_hmma_kernel(
    const __nv_bfloat16* __restrict__ A2, const __nv_bfloat16* __restrict__ B2,
    float* __restrict__ C, int N)
{
    extern __shared__ __nv_bfloat16 sh[];
    // layout: As0, As1, Bs0, Bs1 each 128*PADH halves
    uint32_t shBase = smem_u32(sh);
    const uint32_t TILE_B = 128 * PADH * 2;

    const int tid  = threadIdx.x;
    const int lane = tid & 31;
    const int wid  = tid >> 5;
    const int wm   = wid & 1;      // 0..1 -> m offset 0/64
    const int wn   = wid >> 1;     // 0..3 -> n offset 0/32/64/96

    const int rowBase = blockIdx.y * 128;
    const int colBase = blockIdx.x * 128;
    const __nv_bfloat16* Ag = A2 + (size_t)rowBase * K2DIM;
    const __nv_bfloat16* Bg = B2 + (size_t)colBase * K2DIM;

    float acc[4][4][4];
    #pragma unroll
    for (int i = 0; i < 4; i++)
        #pragma unroll
        for (int j = 0; j < 4; j++)
            #pragma unroll
            for (int q = 0; q < 4; q++) acc[i][j][q] = 0.0f;

    const int nCh = K2DIM / 64;    // 96

    // prefetch stage 0
    ldgsts_tile(shBase + 0 * TILE_B, Ag, 0, tid);
    ldgsts_tile(shBase + 2 * TILE_B, Bg, 0, tid);
    CP_COMMIT();

    const int lrow = (lane & 7) + ((lane >> 3) & 1) * 8;
    const int lcol = (lane >> 4) * 8;

    for (int c = 0; c < nCh; c++) {
        const int s = c & 1;
        if (c + 1 < nCh) {
            const int s2 = s ^ 1;
            ldgsts_tile(shBase + s2 * TILE_B,           Ag, (c + 1) * 64, tid);
            ldgsts_tile(shBase + (2 + s2) * TILE_B,     Bg, (c + 1) * 64, tid);
            CP_COMMIT();
            CP_WAIT(1);
        } else {
            CP_WAIT(0);
        }
        __syncthreads();

        const uint32_t aB = shBase + s * TILE_B;
        const uint32_t bB = shBase + (2 + s) * TILE_B;
        #pragma unroll
        for (int ks = 0; ks < 4; ks++) {
            const int k16 = ks * 16;
            uint32_t af[4][4], bfr[2][4];
            #pragma unroll
            for (int fm = 0; fm < 4; fm++)
                ldmatrix_x4(af[fm][0], af[fm][1], af[fm][2], af[fm][3],
                    aB + (uint32_t)((wm * 64 + fm * 16 + lrow) * PADH + k16 + lcol) * 2);
            #pragma unroll
            for (int fp = 0; fp < 2; fp++)
                ldmatrix_x4(bfr[fp][0], bfr[fp][1], bfr[fp][2], bfr[fp][3],
                    bB + (uint32_t)((wn * 32 + fp * 16 + lrow) * PADH + k16 + lcol) * 2);
            #pragma unroll
            for (int fm = 0; fm < 4; fm++)
                #pragma unroll
                for (int fn = 0; fn < 4; fn++) {
                    uint32_t b0 = (fn & 1) ? bfr[fn >> 1][1] : bfr[fn >> 1][0];
                    uint32_t b1 = (fn & 1) ? bfr[fn >> 1][3] : bfr[fn >> 1][2];
                    mma16816(acc[fm][fn], af[fm], b0, b1);
                }
        }
        __syncthreads();
    }

    // epilogue: per-warp direct stores (float2)
    #pragma unroll
    for (int fm = 0; fm < 4; fm++) {
        #pragma unroll
        for (int fn = 0; fn < 4; fn++) {
            int r0 = rowBase + wm * 64 + fm * 16 + (lane >> 2);
            int c0 = colBase + wn * 32 + fn * 8 + (lane & 3) * 2;
            float2 v01 = make_float2(acc[fm][fn][0], acc[fm][fn][1]);
            float2 v23 = make_float2(acc[fm][fn][2], acc[fm][fn][3]);
            *reinterpret_cast<float2*>(&C[(size_t)r0 * N + c0]) = v01;
            *reinterpret_cast<float2*>(&C[(size_t)(r0 + 8) * N + c0]) = v23;
        }
    }
}

// ---------------------------------------------------------------------------
// RoPE: table build (accurate, tiny) + apply (table lookup)
// ---------------------------------------------------------------------------
__global__ void rope_table_kernel(float* __restrict__ rc, float* __restrict__ rs)
{
    int idx = blockIdx.x * blockDim.x + threadIdx.x;
    if (idx >= T_SEQ * 32) return;
    int t = idx >> 5, i = idx & 31;
    float invf = (float)pow(500000.0, -(double)i / 32.0);
    float angf = (float)t * invf;          // fp32 angle, exactly as reference
    double ang = (double)angf;
    rc[idx] = (float)cos(ang);
    rs[idx] = (float)sin(ang);
}

__global__ void rope_kernel(float* __restrict__ X,
                            const float* __restrict__ rc,
                            const float* __restrict__ rs,
                            int nheads, int rowstride)
{
    int idx = blockIdx.x * blockDim.x + threadIdx.x;
    int total = T_SEQ * nheads * 32;
    if (idx >= total) return;
    int i  = idx & 31;
    int tmp = idx >> 5;
    int h  = tmp % nheads;
    int t  = tmp / nheads;

    float c = rc[t * 32 + i];
    float s = rs[t * 32 + i];
    float* p = X + (size_t)t * rowstride + h * HD + 2 * i;
    float x1 = p[0], x2 = p[1];
    p[0] = x1 * c - x2 * s;
    p[1] = x1 * s + x2 * c;
}

// ---------------------------------------------------------------------------
// Causal flash attention, fp32 (unchanged from passing R4 kernel)
// ---------------------------------------------------------------------------
__global__ __launch_bounds__(128) void flash_kernel(
    const float* __restrict__ Q, const float* __restrict__ Kb,
    const float* __restrict__ Vb, float* __restrict__ O)
{
    const int BM = 128, BKV = 64;
    const float NEG = -1e30f;
    __shared__ float Ks[BKV][HD];
    __shared__ float Vs[BKV][HD];

    int h   = blockIdx.y;
    int kvh = h >> 2;
    int m0  = blockIdx.x * BM;
    int r   = m0 + threadIdx.x;

    float q[HD];
    const float* qrow = Q + (size_t)r * D_MODEL + h * HD;
    #pragma unroll
    for (int d = 0; d < HD; d += 4) {
        float4 t4 = *(const float4*)(qrow + d);
        q[d] = t4.x; q[d + 1] = t4.y; q[d + 2] = t4.z; q[d + 3] = t4.w;
    }

    float acc[HD];
    #pragma unroll
    for (int d = 0; d < HD; d++) acc[d] = 0.0f;
    float m = NEG, l = 0.0f;
    const float scale = 0.125f;

    int kend = m0 + BM;
    for (int j0 = 0; j0 < kend; j0 += BKV) {
        #pragma unroll
        for (int u = 0; u < 8; u++) {
            int idx = threadIdx.x + u * 128;
            int row = idx >> 4;
            int c4  = (idx & 15) << 2;
            const float* ksrc = Kb + (size_t)(j0 + row) * DIM_KV + kvh * HD + c4;
            const float* vsrc = Vb + (size_t)(j0 + row) * DIM_KV + kvh * HD + c4;
            *(float4*)(&Ks[row][c4]) = *(const float4*)ksrc;
            *(float4*)(&Vs[row][c4]) = *(const float4*)vsrc;
        }
        __syncthreads();

        #pragma unroll
        for (int jc = 0; jc < BKV; jc += 16) {
            float s[16];
            #pragma unroll
            for (int jj = 0; jj < 16; jj++) {
                const float* kr = &Ks[jc + jj][0];
                float sum = 0.0f;
                #pragma unroll
                for (int d = 0; d < HD; d++) sum += q[d] * kr[d];
                sum *= scale;
                s[jj] = ((j0 + jc + jj) <= r) ? sum : NEG;
            }
            float tmax = s[0];
            #pragma unroll
            for (int jj = 1; jj < 16; jj++) tmax = fmaxf(tmax, s[jj]);
            float mn = fmaxf(m, tmax);
            float corr = __expf(m - mn);
            m = mn;
            float lsum = 0.0f;
            #pragma unroll
            for (int jj = 0; jj < 16; jj++) {
                s[jj] = __expf(s[jj] - mn);
                lsum += s[jj];
            }
            l = l * corr + lsum;
            #pragma unroll
            for (int d = 0; d < HD; d++) acc[d] *= corr;
            #pragma unroll
            for (int jj = 0; jj < 16; jj++) {
                float pv = s[jj];
                const float* vr = &Vs[jc + jj][0];
                #pragma unroll
                for (int d = 0; d < HD; d++) acc[d] += pv * vr[d];
            }
        }
        __syncthreads();
    }

    float invl = 1.0f / l;
    float* orow = O + (size_t)r * D_MODEL + h * HD;
    #pragma unroll
    for (int d = 0; d < HD; d += 4) {
        float4 o;
        o.x = acc[d] * invl; o.y = acc[d + 1] * invl;
        o.z = acc[d + 2] * invl; o.w = acc[d + 3] * invl;
        *(float4*)(orow + d) = o;
    }
}

// ---------------------------------------------------------------------------
// Launch (input-order detection kept from the passing R4 kernel)
// ---------------------------------------------------------------------------
extern "C" void kernel_launch(void* const* d_in, const int* in_sizes, int n_in,
                              void* d_out, int out_size)
{
    const float *q_embs, *k_embs, *v_embs, *w_q, *w_k, *w_v, *w_o;
    if (in_sizes[3] == D_MODEL * DIM_KV) {
        k_embs = (const float*)d_in[0];
        q_embs = (const float*)d_in[1];
        v_embs = (const float*)d_in[2];
        w_k    = (const float*)d_in[3];
        w_o    = (const float*)d_in[4];
        w_q    = (const float*)d_in[5];
        w_v    = (const float*)d_in[6];
    } else {
        q_embs = (const float*)d_in[0];
        k_embs = (const float*)d_in[1];
        v_embs = (const float*)d_in[2];
        w_q    = (const float*)d_in[3];
        w_k    = (const float*)d_in[4];
        w_v    = (const float*)d_in[5];
        w_o    = (const float*)d_in[6];
    }
    float* out = (float*)d_out;

    float *Q, *K, *V, *O, *RC, *RS;
    __nv_bfloat16 *A2, *B2;
    cudaGetSymbolAddress((void**)&Q,  g_Q);
    cudaGetSymbolAddress((void**)&K,  g_K);
    cudaGetSymbolAddress((void**)&V,  g_V);
    cudaGetSymbolAddress((void**)&O,  g_O);
    cudaGetSymbolAddress((void**)&A2, g_A2);
    cudaGetSymbolAddress((void**)&B2, g_B2);
    cudaGetSymbolAddress((void**)&RC, g_rc);
    cudaGetSymbolAddress((void**)&RS, g_rs);

    cudaFuncSetAttribute(gemm_hmma_kernel,
                         cudaFuncAttributeMaxDynamicSharedMemorySize,
                         GEMM_SMEM_BYTES);

    const int M = T_SEQ;
    const int convA_blocks = (M * KDIM + 255) / 256;

    // ---- Q projection: Q = q_embs @ w_q  (2048x2048x2048)
    split_a_kernel<<<convA_blocks, 256>>>(q_embs, A2, M);
    split_b_kernel<<<dim3(D_MODEL / 32, KDIM / 32), dim3(32, 8)>>>(w_q, B2, D_MODEL);
    gemm_hmma_kernel<<<dim3(D_MODEL / 128, M / 128), 256, GEMM_SMEM_BYTES>>>(A2, B2, Q, D_MODEL);

    // ---- K projection (2048x512x2048)
    split_a_kernel<<<convA_blocks, 256>>>(k_embs, A2, M);
    split_b_kernel<<<dim3(DIM_KV / 32, KDIM / 32), dim3(32, 8)>>>(w_k, B2, DIM_KV);
    gemm_hmma_kernel<<<dim3(DIM_KV / 128, M / 128), 256, GEMM_SMEM_BYTES>>>(A2, B2, K, DIM_KV);

    // ---- V projection (2048x512x2048)
    split_a_kernel<<<convA_blocks, 256>>>(v_embs, A2, M);
    split_b_kernel<<<dim3(DIM_KV / 32, KDIM / 32), dim3(32, 8)>>>(w_v, B2, DIM_KV);
    gemm_hmma_kernel<<<dim3(DIM_KV / 128, M / 128), 256, GEMM_SMEM_BYTES>>>(A2, B2, V, DIM_KV);

    // ---- RoPE (table + apply)
    rope_table_kernel<<<(T_SEQ * 32 + 255) / 256, 256>>>(RC, RS);
    rope_kernel<<<(T_SEQ * NQH * 32 + 255) / 256, 256>>>(Q, RC, RS, NQH, D_MODEL);
    rope_kernel<<<(T_SEQ * NKVH * 32 + 255) / 256, 256>>>(K, RC, RS, NKVH, DIM_KV);

    // ---- Causal GQA attention
    flash_kernel<<<dim3(T_SEQ / 128, NQH), 128>>>(Q, K, V, O);

    // ---- Output projection: out = O @ w_o (2048x2048x2048)
    split_a_kernel<<<convA_blocks, 256>>>(O, A2, M);
    split_b_kernel<<<dim3(D_MODEL / 32, KDIM / 32), dim3(32, 8)>>>(w_o, B2, D_MODEL);
    gemm_hmma_kernel<<<dim3(D_MODEL / 128, M / 128), 256, GEMM_SMEM_BYTES>>>(A2, B2, out, D_MODEL);
}

// round 7
// speedup vs baseline: 1.6339x; 1.0001x over previous
#include <cuda_runtime.h>
#include <cuda_bf16.h>
#include <math.h>
#include <stdint.h>

#define D_MODEL 2048
#define T_SEQ   2048
#define NQH     32
#define NKVH    8
#define HD      64
#define DIM_KV  512
#define KDIM    2048            // inner dim of every projection GEMM
#define K2DIM   (3*KDIM)        // split-bf16 expanded K = 6144
#define PADH    72              // smem row stride in halves (144B -> conflict-free ldmatrix)

// ---------------------------------------------------------------------------
// Device-global scratch (allocation-free rule)
// ---------------------------------------------------------------------------
__device__ float g_Q[T_SEQ * D_MODEL];
__device__ float g_K[T_SEQ * DIM_KV];
__device__ float g_V[T_SEQ * DIM_KV];
__device__ float g_O[T_SEQ * D_MODEL];
__device__ __nv_bfloat16 g_A2[T_SEQ  * K2DIM];   // split activations [M, 3K]
__device__ __nv_bfloat16 g_B2[D_MODEL * K2DIM];  // split weights^T  [N, 3K]
__device__ float g_rc[T_SEQ * 32];               // rope cos table
__device__ float g_rs[T_SEQ * 32];               // rope sin table

// ---------------------------------------------------------------------------
// PTX helpers: portable sm_80+ instructions only (HMMA path; no tcgen05)
// ---------------------------------------------------------------------------
__device__ __forceinline__ uint32_t smem_u32(const void* p) {
    uint32_t a;
    asm("{ .reg .u64 t; cvta.to.shared.u64 t, %1; cvt.u32.u64 %0, t; }"
        : "=r"(a) : "l"(p));
    return a;
}

__device__ __forceinline__ void ldmatrix_x4(uint32_t& r0, uint32_t& r1,
                                            uint32_t& r2, uint32_t& r3,
                                            uint32_t addr) {
    asm volatile("ldmatrix.sync.aligned.m8n8.x4.shared.b16 {%0,%1,%2,%3}, [%4];"
                 : "=r"(r0), "=r"(r1), "=r"(r2), "=r"(r3) : "r"(addr));
}

__device__ __forceinline__ void mma16816(float* d, const uint32_t* a,
                                         uint32_t b0, uint32_t b1) {
    asm volatile(
        "mma.sync.aligned.m16n8k16.row.col.f32.bf16.bf16.f32 "
        "{%0,%1,%2,%3}, {%4,%5,%6,%7}, {%8,%9}, {%0,%1,%2,%3};"
        : "+f"(d[0]), "+f"(d[1]), "+f"(d[2]), "+f"(d[3])
        : "r"(a[0]), "r"(a[1]), "r"(a[2]), "r"(a[3]), "r"(b0), "r"(b1));
}

__device__ __forceinline__ void cp_async16(uint32_t saddr, const void* gaddr) {
    asm volatile("cp.async.cg.shared.global [%0], [%1], 16;"
                 :: "r"(saddr), "l"(gaddr));
}
#define CP_COMMIT() asm volatile("cp.async.commit_group;" ::: "memory")
#define CP_WAIT(n)  asm volatile("cp.async.wait_group %0;" :: "n"(n) : "memory")

// ---------------------------------------------------------------------------
// Split-bf16 conversion kernels
//   A' [M, 3K]: [hi(X) | lo(X) | hi(X)]
//   B' [N, 3K]: [hi(W^T) | hi(W^T) | lo(W^T)]
//   => A'·B'^T = Ah·Wh + Al·Wh + Ah·Wl ≈ X·W  (err ~2^-16)
// ---------------------------------------------------------------------------
__global__ void split_a_kernel(const float* __restrict__ X,
                               __nv_bfloat16* __restrict__ A2, int M)
{
    int idx = blockIdx.x * blockDim.x + threadIdx.x;
    if (idx >= M * KDIM) return;
    int m = idx / KDIM, k = idx % KDIM;
    float x = X[idx];
    __nv_bfloat16 h = __float2bfloat16(x);
    __nv_bfloat16 l = __float2bfloat16(x - __bfloat162float(h));
    size_t b = (size_t)m * K2DIM;
    A2[b + k]            = h;
    A2[b + KDIM + k]     = l;
    A2[b + 2 * KDIM + k] = h;
}

__global__ void split_b_kernel(const float* __restrict__ W,
                               __nv_bfloat16* __restrict__ B2, int N)
{
    __shared__ float tile[32][33];
    int n0 = blockIdx.x * 32, k0 = blockIdx.y * 32;
    int tx = threadIdx.x, ty = threadIdx.y;   // 32 x 8
    #pragma unroll
    for (int i = 0; i < 32; i += 8)
        tile[ty + i][tx] = W[(size_t)(k0 + ty + i) * N + n0 + tx];
    __syncthreads();
    #pragma unroll
    for (int i = 0; i < 32; i += 8) {
        int n = n0 + ty + i;
        float x = tile[tx][ty + i];           // = W[k0+tx][n]
        __nv_bfloat16 h = __float2bfloat16(x);
        __nv_bfloat16 l = __float2bfloat16(x - __bfloat162float(h));
        size_t b = (size_t)n * K2DIM;
        B2[b + k0 + tx]            = h;
        B2[b + KDIM + k0 + tx]     = h;
        B2[b + 2 * KDIM + k0 + tx] = l;
    }
}

// ---------------------------------------------------------------------------
// HMMA GEMM: C[M,N] = A2[M,3K] @ B2[N,3K]^T, fp32 accumulate.
// CTA tile 128x128, K-chunk 64 (bf16), 128 threads = 4 warps (2x2),
// warp tile 64x64, mma.m16n8k16, cp.async double-buffered smem.
// SMEM rows padded to 72 halves (144B) -> ldmatrix conflict-free.
// 2 CTAs/SM for cross-CTA latency hiding.
// ---------------------------------------------------------------------------
#define GEMM_SMEM_BYTES (4 * 128 * PADH * 2)   // 73728

__device__ __forceinline__ void ldgsts_tile(uint32_t sBase,
                                            const __nv_bfloat16* G,
                                            int k0, int tid)
{
    // 128 rows x 64 halves = 1024 x 16B chunks; 8 per thread (128 threads)
    #pragma unroll
    for (int i = 0; i < 8; i++) {
        int id  = tid + (i << 7);
        int row = id >> 3;
        int c8  = id & 7;
        cp_async16(sBase + (uint32_t)(row * PADH + c8 * 8) * 2,
                   G + (size_t)row * K2DIM + k0 + c8 * 8);
    }
}

__global__ __launch_bounds__(128, 2) void gemm_hmma_kernel(
    const __nv_bfloat16* __restrict__ A2, const __nv_bfloat16* __restrict__ B2,
    float* __restrict__ C, int N)
{
    extern __shared__ __nv_bfloat16 sh[];
    // layout: As0, As1, Bs0, Bs1 each 128*PADH halves
    uint32_t shBase = smem_u32(sh);
    const uint32_t TILE_B = 128 * PADH * 2;

    const int tid  = threadIdx.x;
    const int lane = tid & 31;
    const int wid  = tid >> 5;     // 0..3
    const int wm   = wid & 1;      // m offset 0/64
    const int wn   = wid >> 1;     // n offset 0/64

    const int rowBase = blockIdx.y * 128;
    const int colBase = blockIdx.x * 128;
    const __nv_bfloat16* Ag = A2 + (size_t)rowBase * K2DIM;
    const __nv_bfloat16* Bg = B2 + (size_t)colBase * K2DIM;

    float acc[4][8][4];
    #pragma unroll
    for (int i = 0; i < 4; i++)
        #pragma unroll
        for (int j = 0; j < 8; j++)
            #pragma unroll
            for (int q = 0; q < 4; q++) acc[i][j][q] = 0.0f;

    const int nCh = K2DIM / 64;    // 96

    // prefetch stage 0
    ldgsts_tile(shBase + 0 * TILE_B, Ag, 0, tid);
    ldgsts_tile(shBase + 2 * TILE_B, Bg, 0, tid);
    CP_COMMIT();

    const int lrow = (lane & 7) + ((lane >> 3) & 1) * 8;
    const int lcol = (lane >> 4) * 8;

    for (int c = 0; c < nCh; c++) {
        const int s = c & 1;
        if (c + 1 < nCh) {
            const int s2 = s ^ 1;
            ldgsts_tile(shBase + s2 * TILE_B,       Ag, (c + 1) * 64, tid);
            ldgsts_tile(shBase + (2 + s2) * TILE_B, Bg, (c + 1) * 64, tid);
            CP_COMMIT();
            CP_WAIT(1);
        } else {
            CP_WAIT(0);
        }
        __syncthreads();

        const uint32_t aB = shBase + s * TILE_B;
        const uint32_t bB = shBase + (2 + s) * TILE_B;
        #pragma unroll
        for (int ks = 0; ks < 4; ks++) {
            const int k16 = ks * 16;
            uint32_t af[4][4], bfr[4][4];
            #pragma unroll
            for (int fm = 0; fm < 4; fm++)
                ldmatrix_x4(af[fm][0], af[fm][1], af[fm][2], af[fm][3],
                    aB + (uint32_t)((wm * 64 + fm * 16 + lrow) * PADH + k16 + lcol) * 2);
            #pragma unroll
            for (int fp = 0; fp < 4; fp++)
                ldmatrix_x4(bfr[fp][0], bfr[fp][1], bfr[fp][2], bfr[fp][3],
                    bB + (uint32_t)((wn * 64 + fp * 16 + lrow) * PADH + k16 + lcol) * 2);
            #pragma unroll
            for (int fm = 0; fm < 4; fm++)
                #pragma unroll
                for (int fn = 0; fn < 8; fn++) {
                    uint32_t b0 = (fn & 1) ? bfr[fn >> 1][1] : bfr[fn >> 1][0];
                    uint32_t b1 = (fn & 1) ? bfr[fn >> 1][3] : bfr[fn >> 1][2];
                    mma16816(acc[fm][fn], af[fm], b0, b1);
                }
        }
        __syncthreads();
    }

    // epilogue: per-warp direct stores (float2)
    #pragma unroll
    for (int fm = 0; fm < 4; fm++) {
        #pragma unroll
        for (int fn = 0; fn < 8; fn++) {
            int r0 = rowBase + wm * 64 + fm * 16 + (lane >> 2);
            int c0 = colBase + wn * 64 + fn * 8 + (lane & 3) * 2;
            float2 v01 = make_float2(acc[fm][fn][0], acc[fm][fn][1]);
            float2 v23 = make_float2(acc[fm][fn][2], acc[fm][fn][3]);
            *reinterpret_cast<float2*>(&C[(size_t)r0 * N + c0]) = v01;
            *reinterpret_cast<float2*>(&C[(size_t)(r0 + 8) * N + c0]) = v23;
        }
    }
}

// ---------------------------------------------------------------------------
// RoPE: table build (accurate, tiny) + apply (table lookup)
// ---------------------------------------------------------------------------
__global__ void rope_table_kernel(float* __restrict__ rc, float* __restrict__ rs)
{
    int idx = blockIdx.x * blockDim.x + threadIdx.x;
    if (idx >= T_SEQ * 32) return;
    int t = idx >> 5, i = idx & 31;
    float invf = (float)pow(500000.0, -(double)i / 32.0);
    float angf = (float)t * invf;          // fp32 angle, exactly as reference
    double ang = (double)angf;
    rc[idx] = (float)cos(ang);
    rs[idx] = (float)sin(ang);
}

__global__ void rope_kernel(float* __restrict__ X,
                            const float* __restrict__ rc,
                            const float* __restrict__ rs,
                            int nheads, int rowstride)
{
    int idx = blockIdx.x * blockDim.x + threadIdx.x;
    int total = T_SEQ * nheads * 32;
    if (idx >= total) return;
    int i  = idx & 31;
    int tmp = idx >> 5;
    int h  = tmp % nheads;
    int t  = tmp / nheads;

    float c = rc[t * 32 + i];
    float s = rs[t * 32 + i];
    float* p = X + (size_t)t * rowstride + h * HD + 2 * i;
    float x1 = p[0], x2 = p[1];
    p[0] = x1 * c - x2 * s;
    p[1] = x1 * s + x2 * c;
}

// ---------------------------------------------------------------------------
// Causal flash attention, fp32 (unchanged from passing kernel)
// ---------------------------------------------------------------------------
__global__ __launch_bounds__(128) void flash_kernel(
    const float* __restrict__ Q, const float* __restrict__ Kb,
    const float* __restrict__ Vb, float* __restrict__ O)
{
    const int BM = 128, BKV = 64;
    const float NEG = -1e30f;
    __shared__ float Ks[BKV][HD];
    __shared__ float Vs[BKV][HD];

    int h   = blockIdx.y;
    int kvh = h >> 2;
    int m0  = blockIdx.x * BM;
    int r   = m0 + threadIdx.x;

    float q[HD];
    const float* qrow = Q + (size_t)r * D_MODEL + h * HD;
    #pragma unroll
    for (int d = 0; d < HD; d += 4) {
        float4 t4 = *(const float4*)(qrow + d);
        q[d] = t4.x; q[d + 1] = t4.y; q[d + 2] = t4.z; q[d + 3] = t4.w;
    }

    float acc[HD];
    #pragma unroll
    for (int d = 0; d < HD; d++) acc[d] = 0.0f;
    float m = NEG, l = 0.0f;
    const float scale = 0.125f;

    int kend = m0 + BM;
    for (int j0 = 0; j0 < kend; j0 += BKV) {
        #pragma unroll
        for (int u = 0; u < 8; u++) {
            int idx = threadIdx.x + u * 128;
            int row = idx >> 4;
            int c4  = (idx & 15) << 2;
            const float* ksrc = Kb + (size_t)(j0 + row) * DIM_KV + kvh * HD + c4;
            const float* vsrc = Vb + (size_t)(j0 + row) * DIM_KV + kvh * HD + c4;
            *(float4*)(&Ks[row][c4]) = *(const float4*)ksrc;
            *(float4*)(&Vs[row][c4]) = *(const float4*)vsrc;
        }
        __syncthreads();

        #pragma unroll
        for (int jc = 0; jc < BKV; jc += 16) {
            float s[16];
            #pragma unroll
            for (int jj = 0; jj < 16; jj++) {
                const float* kr = &Ks[jc + jj][0];
                float sum = 0.0f;
                #pragma unroll
                for (int d = 0; d < HD; d++) sum += q[d] * kr[d];
                sum *= scale;
                s[jj] = ((j0 + jc + jj) <= r) ? sum : NEG;
            }
            float tmax = s[0];
            #pragma unroll
            for (int jj = 1; jj < 16; jj++) tmax = fmaxf(tmax, s[jj]);
            float mn = fmaxf(m, tmax);
            float corr = __expf(m - mn);
            m = mn;
            float lsum = 0.0f;
            #pragma unroll
            for (int jj = 0; jj < 16; jj++) {
                s[jj] = __expf(s[jj] - mn);
                lsum += s[jj];
            }
            l = l * corr + lsum;
            #pragma unroll
            for (int d = 0; d < HD; d++) acc[d] *= corr;
            #pragma unroll
            for (int jj = 0; jj < 16; jj++) {
                float pv = s[jj];
                const float* vr = &Vs[jc + jj][0];
                #pragma unroll
                for (int d = 0; d < HD; d++) acc[d] += pv * vr[d];
            }
        }
        __syncthreads();
    }

    float invl = 1.0f / l;
    float* orow = O + (size_t)r * D_MODEL + h * HD;
    #pragma unroll
    for (int d = 0; d < HD; d += 4) {
        float4 o;
        o.x = acc[d] * invl; o.y = acc[d + 1] * invl;
        o.z = acc[d + 2] * invl; o.w = acc[d + 3] * invl;
        *(float4*)(orow + d) = o;
    }
}

// ---------------------------------------------------------------------------
// Launch (input-order detection kept from the passing kernel)
// ---------------------------------------------------------------------------
extern "C" void kernel_launch(void* const* d_in, const int* in_sizes, int n_in,
                              void* d_out, int out_size)
{
    const float *q_embs, *k_embs, *v_embs, *w_q, *w_k, *w_v, *w_o;
    if (in_sizes[3] == D_MODEL * DIM_KV) {
        k_embs = (const float*)d_in[0];
        q_embs = (const float*)d_in[1];
        v_embs = (const float*)d_in[2];
        w_k    = (const float*)d_in[3];
        w_o    = (const float*)d_in[4];
        w_q    = (const float*)d_in[5];
        w_v    = (const float*)d_in[6];
    } else {
        q_embs = (const float*)d_in[0];
        k_embs = (const float*)d_in[1];
        v_embs = (const float*)d_in[2];
        w_q    = (const float*)d_in[3];
        w_k    = (const float*)d_in[4];
        w_v    = (const float*)d_in[5];
        w_o    = (const float*)d_in[6];
    }
    float* out = (float*)d_out;

    float *Q, *K, *V, *O, *RC, *RS;
    __nv_bfloat16 *A2, *B2;
    cudaGetSymbolAddress((void**)&Q,  g_Q);
    cudaGetSymbolAddress((void**)&K,  g_K);
    cudaGetSymbolAddress((void**)&V,  g_V);
    cudaGetSymbolAddress((void**)&O,  g_O);
    cudaGetSymbolAddress((void**)&A2, g_A2);
    cudaGetSymbolAddress((void**)&B2, g_B2);
    cudaGetSymbolAddress((void**)&RC, g_rc);
    cudaGetSymbolAddress((void**)&RS, g_rs);

    cudaFuncSetAttribute(gemm_hmma_kernel,
                         cudaFuncAttributeMaxDynamicSharedMemorySize,
                         GEMM_SMEM_BYTES);

    const int M = T_SEQ;
    const int convA_blocks = (M * KDIM + 255) / 256;

    // ---- Q projection: Q = q_embs @ w_q  (2048x2048x2048)
    split_a_kernel<<<convA_blocks, 256>>>(q_embs, A2, M);
    split_b_kernel<<<dim3(D_MODEL / 32, KDIM / 32), dim3(32, 8)>>>(w_q, B2, D_MODEL);
    gemm_hmma_kernel<<<dim3(D_MODEL / 128, M / 128), 128, GEMM_SMEM_BYTES>>>(A2, B2, Q, D_MODEL);

    // ---- K projection (2048x512x2048)
    split_a_kernel<<<convA_blocks, 256>>>(k_embs, A2, M);
    split_b_kernel<<<dim3(DIM_KV / 32, KDIM / 32), dim3(32, 8)>>>(w_k, B2, DIM_KV);
    gemm_hmma_kernel<<<dim3(DIM_KV / 128, M / 128), 128, GEMM_SMEM_BYTES>>>(A2, B2, K, DIM_KV);

    // ---- V projection (2048x512x2048)
    split_a_kernel<<<convA_blocks, 256>>>(v_embs, A2, M);
    split_b_kernel<<<dim3(DIM_KV / 32, KDIM / 32), dim3(32, 8)>>>(w_v, B2, DIM_KV);
    gemm_hmma_kernel<<<dim3(DIM_KV / 128, M / 128), 128, GEMM_SMEM_BYTES>>>(A2, B2, V, DIM_KV);

    // ---- RoPE (table + apply)
    rope_table_kernel<<<(T_SEQ * 32 + 255) / 256, 256>>>(RC, RS);
    rope_kernel<<<(T_SEQ * NQH * 32 + 255) / 256, 256>>>(Q, RC, RS, NQH, D_MODEL);
    rope_kernel<<<(T_SEQ * NKVH * 32 + 255) / 256, 256>>>(K, RC, RS, NKVH, DIM_KV);

    // ---- Causal GQA attention
    flash_kernel<<<dim3(T_SEQ / 128, NQH), 128>>>(Q, K, V, O);

    // ---- Output projection: out = O @ w_o (2048x2048x2048)
    split_a_kernel<<<convA_blocks, 256>>>(O, A2, M);
    split_b_kernel<<<dim3(D_MODEL / 32, KDIM / 32), dim3(32, 8)>>>(w_o, B2, D_MODEL);
    gemm_hmma_kernel<<<dim3(D_MODEL / 128, M / 128), 128, GEMM_SMEM_BYTES>>>(A2, B2, out, D_MODEL);
}